// round 1
// baseline (speedup 1.0000x reference)
#include <cuda_runtime.h>
#include <cstddef>
#include <math.h>

#define DIM   768
#define TSEQ  1024
#define BATCH 4
#define HEADS 12
#define HDIM  64
#define QKVN  (3 * DIM)   // 2304
#define MROWS (BATCH * TSEQ) // 4096
#define EPS   1e-5f

// ---------------- scratch (static device globals; no allocation) -------------
__device__ float g_qkv_c [MROWS * QKVN];  // 4096 x 2304
__device__ float g_qkv_ac[MROWS * QKVN];
__device__ float g_att_c [MROWS * DIM];   // 4096 x 768
__device__ float g_att_ac[MROWS * DIM];
__device__ float g_y     [MROWS * DIM];

// ---------------- generic fp32 GEMM: C = A[M,K] @ W[K,N] + bias (+ addend) ---
#define BM 128
#define BN 64
#define BK 16

__global__ void gemm_bias_kernel(const float* __restrict__ A,
                                 const float* __restrict__ W,
                                 const float* __restrict__ bias,
                                 const float* __restrict__ addend, // nullable: += addend[r*N+c]
                                 float* __restrict__ C,
                                 int M, int K, int N, int accum)
{
    __shared__ float Ast[BK][BM];  // A tile, transposed
    __shared__ float Ws [BK][BN];

    const int tid  = threadIdx.x;           // 256 threads
    const int ty   = tid >> 4;              // 0..15 (row group: 8 rows)
    const int tx   = tid & 15;              // 0..15 (col group: 4 cols)
    const int row0 = blockIdx.y * BM;
    const int col0 = blockIdx.x * BN;

    float acc[8][4];
    #pragma unroll
    for (int i = 0; i < 8; i++)
        #pragma unroll
        for (int j = 0; j < 4; j++) acc[i][j] = 0.f;

    for (int k0 = 0; k0 < K; k0 += BK) {
        // --- load A tile (128x16) as 512 float4 ---
        #pragma unroll
        for (int i = 0; i < 2; i++) {
            int idx = tid + i * 256;        // 0..511
            int r   = idx >> 2;             // 0..127
            int c4  = idx & 3;              // 0..3
            float4 f = *(const float4*)(A + (size_t)(row0 + r) * K + k0 + c4 * 4);
            Ast[c4 * 4 + 0][r] = f.x;
            Ast[c4 * 4 + 1][r] = f.y;
            Ast[c4 * 4 + 2][r] = f.z;
            Ast[c4 * 4 + 3][r] = f.w;
        }
        // --- load W tile (16x64) as 256 float4 ---
        {
            int kr = tid >> 4;              // 0..15
            int c4 = tid & 15;              // 0..15
            *(float4*)&Ws[kr][c4 * 4] =
                *(const float4*)(W + (size_t)(k0 + kr) * N + col0 + c4 * 4);
        }
        __syncthreads();

        #pragma unroll
        for (int kk = 0; kk < BK; kk++) {
            float a[8];
            #pragma unroll
            for (int i = 0; i < 8; i++) a[i] = Ast[kk][ty * 8 + i];
            float4 b4 = *(float4*)&Ws[kk][tx * 4];
            float b[4] = {b4.x, b4.y, b4.z, b4.w};
            #pragma unroll
            for (int i = 0; i < 8; i++)
                #pragma unroll
                for (int j = 0; j < 4; j++)
                    acc[i][j] = fmaf(a[i], b[j], acc[i][j]);
        }
        __syncthreads();
    }

    // --- epilogue ---
    #pragma unroll
    for (int i = 0; i < 8; i++) {
        int r = row0 + ty * 8 + i;
        #pragma unroll
        for (int j = 0; j < 4; j++) {
            int c = col0 + tx * 4 + j;
            float v = acc[i][j] + bias[c];
            if (addend) v += addend[(size_t)r * N + c];
            size_t o = (size_t)r * N + c;
            if (accum) C[o] += v; else C[o] = v;
        }
    }
}

// ---------------- flash-style fp32 attention ---------------------------------
// grid: (T/64, HEADS, BATCH), block: 128 threads = 64 rows x 2 half-threads.
// qkv layout per row t: [3, H, 64] -> q at h*64, k at 768+h*64, v at 1536+h*64.
__global__ void attn_kernel(const float* __restrict__ qkv,
                            float* __restrict__ out, int causal)
{
    __shared__ float Ks[64][64];
    __shared__ float Vs[64][64];

    const int tid  = threadIdx.x;
    const int half = tid & 1;      // which 32 of Dh
    const int row  = tid >> 1;     // 0..63 query row within tile
    const int qt = blockIdx.x, h = blockIdx.y, b = blockIdx.z;
    const int ti = qt * 64 + row;

    // load scaled q half-row into registers
    float q[32];
    {
        const float* qp = qkv + ((size_t)(b * TSEQ + ti)) * QKVN + h * HDIM + half * 32;
        #pragma unroll
        for (int d = 0; d < 32; d++) q[d] = qp[d] * 0.125f;  // 1/sqrt(64)
    }

    float m = -INFINITY, l = 0.f;
    float acc[32];
    #pragma unroll
    for (int d = 0; d < 32; d++) acc[d] = 0.f;

    const int kt0 = causal ? 0  : qt;
    const int kt1 = causal ? qt : (TSEQ / 64 - 1);

    for (int kt = kt0; kt <= kt1; kt++) {
        // cooperative K/V tile load: each thread loads one half-row (8 float4 each)
        {
            const float* kp = qkv + ((size_t)(b * TSEQ + kt * 64 + row)) * QKVN
                              + DIM + h * HDIM + half * 32;
            const float* vp = kp + DIM;
            float4* kd = (float4*)&Ks[row][half * 32];
            float4* vd = (float4*)&Vs[row][half * 32];
            #pragma unroll
            for (int i = 0; i < 8; i++) {
                kd[i] = ((const float4*)kp)[i];
                vd[i] = ((const float4*)vp)[i];
            }
        }
        __syncthreads();

        const bool diag = (kt == qt);

        #pragma unroll 1
        for (int j0 = 0; j0 < 64; j0 += 8) {
            float s[8];
            #pragma unroll
            for (int jj = 0; jj < 8; jj++) {
                const float4* kr = (const float4*)&Ks[j0 + jj][half * 32];
                float ss = 0.f;
                #pragma unroll
                for (int dd = 0; dd < 8; dd++) {
                    float4 kv = kr[dd];
                    ss = fmaf(q[dd * 4 + 0], kv.x, ss);
                    ss = fmaf(q[dd * 4 + 1], kv.y, ss);
                    ss = fmaf(q[dd * 4 + 2], kv.z, ss);
                    ss = fmaf(q[dd * 4 + 3], kv.w, ss);
                }
                ss += __shfl_xor_sync(0xffffffffu, ss, 1);  // combine halves
                if (diag) {
                    int tj = kt * 64 + j0 + jj;
                    bool valid = causal ? (tj <= ti) : (tj >= ti);
                    if (!valid) ss = -INFINITY;
                }
                s[jj] = ss;
            }
            float cm = s[0];
            #pragma unroll
            for (int jj = 1; jj < 8; jj++) cm = fmaxf(cm, s[jj]);
            float m_new = fmaxf(m, cm);
            if (m_new > -INFINITY) {
                float corr = __expf(m - m_new);
                float p[8], ps = 0.f;
                #pragma unroll
                for (int jj = 0; jj < 8; jj++) { p[jj] = __expf(s[jj] - m_new); ps += p[jj]; }
                l = l * corr + ps;
                #pragma unroll
                for (int d = 0; d < 32; d++) acc[d] *= corr;
                #pragma unroll
                for (int jj = 0; jj < 8; jj++) {
                    const float4* vr = (const float4*)&Vs[j0 + jj][half * 32];
                    float pj = p[jj];
                    #pragma unroll
                    for (int dd = 0; dd < 8; dd++) {
                        float4 vv = vr[dd];
                        acc[dd * 4 + 0] = fmaf(pj, vv.x, acc[dd * 4 + 0]);
                        acc[dd * 4 + 1] = fmaf(pj, vv.y, acc[dd * 4 + 1]);
                        acc[dd * 4 + 2] = fmaf(pj, vv.z, acc[dd * 4 + 2]);
                        acc[dd * 4 + 3] = fmaf(pj, vv.w, acc[dd * 4 + 3]);
                    }
                }
                m = m_new;
            }
        }
        __syncthreads();
    }

    const float inv = 1.f / l;
    float* op = out + ((size_t)(b * TSEQ + ti)) * DIM + h * HDIM + half * 32;
    #pragma unroll
    for (int d = 0; d < 32; d++) op[d] = acc[d] * inv;
}

// ---------------- LayerNorm ---------------------------------------------------
__global__ void ln_kernel(const float* __restrict__ y,
                          const float* __restrict__ gamma,
                          const float* __restrict__ beta,
                          float* __restrict__ out)
{
    __shared__ float s_sum[256];
    __shared__ float s_sq[256];
    const int row = blockIdx.x;
    const int tid = threadIdx.x;
    const float* yr = y + (size_t)row * DIM;

    float v0 = yr[tid], v1 = yr[tid + 256], v2 = yr[tid + 512];
    float su = v0 + v1 + v2;
    float sq = v0 * v0 + v1 * v1 + v2 * v2;
    s_sum[tid] = su; s_sq[tid] = sq;
    __syncthreads();
    for (int off = 128; off > 0; off >>= 1) {
        if (tid < off) { s_sum[tid] += s_sum[tid + off]; s_sq[tid] += s_sq[tid + off]; }
        __syncthreads();
    }
    const float mu  = s_sum[0] * (1.f / DIM);
    const float var = s_sq[0] * (1.f / DIM) - mu * mu;
    const float rstd = rsqrtf(var + EPS);

    float* orow = out + (size_t)row * DIM;
    orow[tid]       = (v0 - mu) * rstd * gamma[tid]       + beta[tid];
    orow[tid + 256] = (v1 - mu) * rstd * gamma[tid + 256] + beta[tid + 256];
    orow[tid + 512] = (v2 - mu) * rstd * gamma[tid + 512] + beta[tid + 512];
}

// ---------------- launch ------------------------------------------------------
extern "C" void kernel_launch(void* const* d_in, const int* in_sizes, int n_in,
                              void* d_out, int out_size)
{
    const float* x       = (const float*)d_in[0];
    const float* Wqkv_c  = (const float*)d_in[1];
    const float* bqkv_c  = (const float*)d_in[2];
    const float* Wp_c    = (const float*)d_in[3];
    const float* bp_c    = (const float*)d_in[4];
    const float* Wqkv_ac = (const float*)d_in[5];
    const float* bqkv_ac = (const float*)d_in[6];
    const float* Wp_ac   = (const float*)d_in[7];
    const float* bp_ac   = (const float*)d_in[8];
    const float* gamma   = (const float*)d_in[9];
    const float* beta    = (const float*)d_in[10];
    float* out = (float*)d_out;

    float *qkvc, *qkvac, *attc, *attac, *yb;
    cudaGetSymbolAddress((void**)&qkvc,  g_qkv_c);
    cudaGetSymbolAddress((void**)&qkvac, g_qkv_ac);
    cudaGetSymbolAddress((void**)&attc,  g_att_c);
    cudaGetSymbolAddress((void**)&attac, g_att_ac);
    cudaGetSymbolAddress((void**)&yb,    g_y);

    // QKV projections (both branches)
    dim3 gq(QKVN / BN, MROWS / BM);
    gemm_bias_kernel<<<gq, 256>>>(x, Wqkv_c,  bqkv_c,  nullptr, qkvc,  MROWS, DIM, QKVN, 0);
    gemm_bias_kernel<<<gq, 256>>>(x, Wqkv_ac, bqkv_ac, nullptr, qkvac, MROWS, DIM, QKVN, 0);

    // attention (causal / anti-causal)
    dim3 ga(TSEQ / 64, HEADS, BATCH);
    attn_kernel<<<ga, 128>>>(qkvc,  attc,  1);
    attn_kernel<<<ga, 128>>>(qkvac, attac, 0);

    // output projections fused with residual: y = x + att_c@Wp_c + bp_c, then += ac branch
    dim3 gp(DIM / BN, MROWS / BM);
    gemm_bias_kernel<<<gp, 256>>>(attc,  Wp_c,  bp_c,  x,       yb, MROWS, DIM, DIM, 0);
    gemm_bias_kernel<<<gp, 256>>>(attac, Wp_ac, bp_ac, nullptr, yb, MROWS, DIM, DIM, 1);

    // LayerNorm -> d_out
    ln_kernel<<<MROWS, 256>>>(yb, gamma, beta, out);
}

// round 2
// speedup vs baseline: 2.3585x; 2.3585x over previous
#include <cuda_runtime.h>
#include <cstdint>
#include <cstddef>
#include <math.h>

#define DIM   768
#define TSEQ  1024
#define BATCH 4
#define HEADS 12
#define HDIM  64
#define QKVN  (3 * DIM)      // 2304
#define MROWS (BATCH * TSEQ) // 4096
#define EPS   1e-5f

// ---------------- scratch (static device globals; no allocation) -------------
__device__ float g_qkv_c [MROWS * QKVN];
__device__ float g_qkv_ac[MROWS * QKVN];
__device__ float g_att_c [MROWS * DIM];
__device__ float g_att_ac[MROWS * DIM];
__device__ float g_y     [MROWS * DIM];

// ---------------- tf32 helpers ------------------------------------------------
__device__ __forceinline__ uint32_t f2tf32(float f) {
    uint32_t r;
    asm("cvt.rna.tf32.f32 %0, %1;" : "=r"(r) : "f"(f));
    return r;
}

__device__ __forceinline__ void mma_tf32(float c[4], const uint32_t a[4], const uint32_t b[2]) {
    asm volatile(
        "mma.sync.aligned.m16n8k8.row.col.f32.tf32.tf32.f32 "
        "{%0,%1,%2,%3}, {%4,%5,%6,%7}, {%8,%9}, {%0,%1,%2,%3};"
        : "+f"(c[0]), "+f"(c[1]), "+f"(c[2]), "+f"(c[3])
        : "r"(a[0]), "r"(a[1]), "r"(a[2]), "r"(a[3]), "r"(b[0]), "r"(b[1]));
}

// ---------------- tf32 tensor-core GEMM: C = A[M,K]@W[K,N] + bias (+addend) --
// BM=128, BN=128, BK=32. 256 threads = 8 warps, warp tile 64x32 (2x4 warp grid),
// each warp: 4 mtiles (m16) x 4 ntiles (n8), k in steps of 8.
#define GBM 128
#define GBN 128
#define GBK 32

__global__ void __launch_bounds__(256, 2)
gemm_tf32_kernel(const float* __restrict__ A,
                 const float* __restrict__ W,
                 const float* __restrict__ bias,
                 const float* __restrict__ addend,   // nullable
                 float* __restrict__ C,
                 int M, int K, int N, int accum)
{
    __shared__ uint32_t As[GBM][GBK + 4];   // 128 x 36
    __shared__ uint32_t Bs[GBK][GBN + 4];   // 32 x 132

    const int tid  = threadIdx.x;
    const int warp = tid >> 5;
    const int lane = tid & 31;
    const int wr   = warp >> 2;   // 0..1
    const int wc   = warp & 3;    // 0..3
    const int g    = lane >> 2;   // 0..7
    const int t4   = lane & 3;    // 0..3
    const int row0 = blockIdx.y * GBM;
    const int col0 = blockIdx.x * GBN;

    float acc[4][4][4];
    #pragma unroll
    for (int mi = 0; mi < 4; mi++)
        #pragma unroll
        for (int ni = 0; ni < 4; ni++)
            #pragma unroll
            for (int q = 0; q < 4; q++) acc[mi][ni][q] = 0.f;

    for (int k0 = 0; k0 < K; k0 += GBK) {
        // A tile: 128x32 = 1024 float4, 4 per thread
        #pragma unroll
        for (int i = 0; i < 4; i++) {
            int idx = tid + i * 256;
            int r   = idx >> 3;
            int c   = (idx & 7) * 4;
            float4 f = *(const float4*)(A + (size_t)(row0 + r) * K + k0 + c);
            As[r][c + 0] = f2tf32(f.x);
            As[r][c + 1] = f2tf32(f.y);
            As[r][c + 2] = f2tf32(f.z);
            As[r][c + 3] = f2tf32(f.w);
        }
        // B tile: 32x128 = 1024 float4, 4 per thread
        #pragma unroll
        for (int i = 0; i < 4; i++) {
            int idx = tid + i * 256;
            int r   = idx >> 5;
            int c   = (idx & 31) * 4;
            float4 f = *(const float4*)(W + (size_t)(k0 + r) * N + col0 + c);
            Bs[r][c + 0] = f2tf32(f.x);
            Bs[r][c + 1] = f2tf32(f.y);
            Bs[r][c + 2] = f2tf32(f.z);
            Bs[r][c + 3] = f2tf32(f.w);
        }
        __syncthreads();

        #pragma unroll
        for (int ks = 0; ks < 4; ks++) {
            const int kb = ks * 8;
            uint32_t af[4][4];
            #pragma unroll
            for (int mi = 0; mi < 4; mi++) {
                int ar = wr * 64 + mi * 16 + g;
                af[mi][0] = As[ar][kb + t4];
                af[mi][1] = As[ar + 8][kb + t4];
                af[mi][2] = As[ar][kb + t4 + 4];
                af[mi][3] = As[ar + 8][kb + t4 + 4];
            }
            uint32_t bf[4][2];
            #pragma unroll
            for (int ni = 0; ni < 4; ni++) {
                int bc = wc * 32 + ni * 8 + g;
                bf[ni][0] = Bs[kb + t4][bc];
                bf[ni][1] = Bs[kb + t4 + 4][bc];
            }
            #pragma unroll
            for (int mi = 0; mi < 4; mi++)
                #pragma unroll
                for (int ni = 0; ni < 4; ni++)
                    mma_tf32(acc[mi][ni], af[mi], bf[ni]);
        }
        __syncthreads();
    }

    // epilogue
    #pragma unroll
    for (int mi = 0; mi < 4; mi++) {
        #pragma unroll
        for (int ni = 0; ni < 4; ni++) {
            int r = row0 + wr * 64 + mi * 16 + g;
            int c = col0 + wc * 32 + ni * 8 + 2 * t4;
            #pragma unroll
            for (int q = 0; q < 4; q++) {
                int rr = r + (q >> 1) * 8;
                int cc = c + (q & 1);
                float v = acc[mi][ni][q] + bias[cc];
                size_t o = (size_t)rr * N + cc;
                if (addend) v += addend[o];
                if (accum) C[o] += v; else C[o] = v;
            }
        }
    }
}

// ---------------- flash attention, GEMM-structured fp32 -----------------------
// grid (T/64, HEADS, BATCH), 128 threads. Per key tile:
//   S^T[j][i] = sum_d K[j][d] Q[i][d]   (8x4 microtile, ty=rows of j, tx=cols of i)
//   softmax over j per column i (2 threads per column)
//   O[i][d]  += P[i][j] V[j][d]         (same microtile: ty=rows of i, tx=cols of d)
#define APAD 68

__global__ void __launch_bounds__(128, 3)
attn_kernel(const float* __restrict__ qkv, float* __restrict__ out, int causal)
{
    extern __shared__ float sm[];
    float* Qts = sm;                 // [64][APAD]  Q^T (scaled)
    float* Kts = Qts + 64 * APAD;    // [64][APAD]  K^T
    float* Vs  = Kts + 64 * APAD;    // [64][APAD]  V (natural)
    float* Ps  = Vs  + 64 * APAD;    // [64][APAD]  S^T -> P^T
    float* corr_sh = Ps + 64 * APAD; // [64]
    float* linv_sh = corr_sh + 64;   // [64]

    const int tid  = threadIdx.x;
    const int ty   = tid >> 4;   // 0..7
    const int tx   = tid & 15;   // 0..15
    const int half = tid & 1;
    const int rw   = tid >> 1;   // 0..63 (row for loads / column for softmax)
    const int qt = blockIdx.x, h = blockIdx.y, b = blockIdx.z;

    // load Q tile transposed + scaled
    {
        const float* qp = qkv + ((size_t)(b * TSEQ + qt * 64 + rw)) * QKVN + h * HDIM + half * 32;
        #pragma unroll
        for (int i = 0; i < 8; i++) {
            float4 f = ((const float4*)qp)[i];
            int c = half * 32 + i * 4;
            Qts[(c + 0) * APAD + rw] = f.x * 0.125f;
            Qts[(c + 1) * APAD + rw] = f.y * 0.125f;
            Qts[(c + 2) * APAD + rw] = f.z * 0.125f;
            Qts[(c + 3) * APAD + rw] = f.w * 0.125f;
        }
    }

    float m = -INFINITY, l = 0.f;
    float acc[8][4];
    #pragma unroll
    for (int i = 0; i < 8; i++)
        #pragma unroll
        for (int j = 0; j < 4; j++) acc[i][j] = 0.f;

    const int kt0 = causal ? 0  : qt;
    const int kt1 = causal ? qt : (TSEQ / 64 - 1);
    const int i_g = qt * 64 + rw;    // softmax column (global)

    for (int kt = kt0; kt <= kt1; kt++) {
        // load K (transposed) and V (natural)
        {
            const float* kp = qkv + ((size_t)(b * TSEQ + kt * 64 + rw)) * QKVN
                              + DIM + h * HDIM + half * 32;
            const float* vp = kp + DIM;
            #pragma unroll
            for (int i = 0; i < 8; i++) {
                float4 f = ((const float4*)kp)[i];
                int c = half * 32 + i * 4;
                Kts[(c + 0) * APAD + rw] = f.x;
                Kts[(c + 1) * APAD + rw] = f.y;
                Kts[(c + 2) * APAD + rw] = f.z;
                Kts[(c + 3) * APAD + rw] = f.w;
                ((float4*)&Vs[rw * APAD + half * 32])[i] = ((const float4*)vp)[i];
            }
        }
        __syncthreads();

        // S^T GEMM: st[j'][i'] for j = ty*8+j', i = tx*4+i'
        float st[8][4];
        #pragma unroll
        for (int i = 0; i < 8; i++)
            #pragma unroll
            for (int j = 0; j < 4; j++) st[i][j] = 0.f;
        #pragma unroll 8
        for (int kk = 0; kk < 64; kk++) {
            float4 a0 = *(const float4*)&Kts[kk * APAD + ty * 8];
            float4 a1 = *(const float4*)&Kts[kk * APAD + ty * 8 + 4];
            float4 bv = *(const float4*)&Qts[kk * APAD + tx * 4];
            float a[8] = {a0.x, a0.y, a0.z, a0.w, a1.x, a1.y, a1.z, a1.w};
            float bb[4] = {bv.x, bv.y, bv.z, bv.w};
            #pragma unroll
            for (int i = 0; i < 8; i++)
                #pragma unroll
                for (int j = 0; j < 4; j++)
                    st[i][j] = fmaf(a[i], bb[j], st[i][j]);
        }
        #pragma unroll
        for (int i = 0; i < 8; i++)
            *((float4*)&Ps[(ty * 8 + i) * APAD + tx * 4]) =
                make_float4(st[i][0], st[i][1], st[i][2], st[i][3]);
        __syncthreads();

        // online softmax per column i = rw, this thread handles j in [half*32, +32)
        {
            const bool diag = (kt == qt);
            float sv[32];
            float tm = -INFINITY;
            #pragma unroll
            for (int jj = 0; jj < 32; jj++) {
                int j = half * 32 + jj;
                float s = Ps[j * APAD + rw];
                if (diag) {
                    int jg = kt * 64 + j;
                    bool valid = causal ? (jg <= i_g) : (jg >= i_g);
                    if (!valid) s = -INFINITY;
                }
                sv[jj] = s;
                tm = fmaxf(tm, s);
            }
            tm = fmaxf(tm, __shfl_xor_sync(0xffffffffu, tm, 1));
            float m_new = fmaxf(m, tm);
            float corr = __expf(m - m_new);
            float ps = 0.f;
            #pragma unroll
            for (int jj = 0; jj < 32; jj++) {
                float p = __expf(sv[jj] - m_new);
                Ps[(half * 32 + jj) * APAD + rw] = p;
                ps += p;
            }
            ps += __shfl_xor_sync(0xffffffffu, ps, 1);
            l = l * corr + ps;
            m = m_new;
            if (half == 0) corr_sh[rw] = corr;
        }
        __syncthreads();

        // rescale O, then O += P V
        {
            float cv[8];
            #pragma unroll
            for (int i = 0; i < 8; i++) cv[i] = corr_sh[ty * 8 + i];
            #pragma unroll
            for (int i = 0; i < 8; i++)
                #pragma unroll
                for (int j = 0; j < 4; j++) acc[i][j] *= cv[i];
        }
        #pragma unroll 8
        for (int kk = 0; kk < 64; kk++) {
            float4 a0 = *(const float4*)&Ps[kk * APAD + ty * 8];
            float4 a1 = *(const float4*)&Ps[kk * APAD + ty * 8 + 4];
            float4 bv = *(const float4*)&Vs[kk * APAD + tx * 4];
            float a[8] = {a0.x, a0.y, a0.z, a0.w, a1.x, a1.y, a1.z, a1.w};
            float bb[4] = {bv.x, bv.y, bv.z, bv.w};
            #pragma unroll
            for (int i = 0; i < 8; i++)
                #pragma unroll
                for (int j = 0; j < 4; j++)
                    acc[i][j] = fmaf(a[i], bb[j], acc[i][j]);
        }
        __syncthreads();
    }

    if (half == 0) linv_sh[rw] = 1.f / l;
    __syncthreads();

    #pragma unroll
    for (int i = 0; i < 8; i++) {
        float li = linv_sh[ty * 8 + i];
        int rowg = b * TSEQ + qt * 64 + ty * 8 + i;
        float4 v = make_float4(acc[i][0] * li, acc[i][1] * li, acc[i][2] * li, acc[i][3] * li);
        *((float4*)(out + (size_t)rowg * DIM + h * HDIM + tx * 4)) = v;
    }
}

// ---------------- LayerNorm ---------------------------------------------------
__global__ void ln_kernel(const float* __restrict__ y,
                          const float* __restrict__ gamma,
                          const float* __restrict__ beta,
                          float* __restrict__ out)
{
    __shared__ float s_sum[256];
    __shared__ float s_sq[256];
    const int row = blockIdx.x;
    const int tid = threadIdx.x;
    const float* yr = y + (size_t)row * DIM;

    float v0 = yr[tid], v1 = yr[tid + 256], v2 = yr[tid + 512];
    float su = v0 + v1 + v2;
    float sq = v0 * v0 + v1 * v1 + v2 * v2;
    s_sum[tid] = su; s_sq[tid] = sq;
    __syncthreads();
    for (int off = 128; off > 0; off >>= 1) {
        if (tid < off) { s_sum[tid] += s_sum[tid + off]; s_sq[tid] += s_sq[tid + off]; }
        __syncthreads();
    }
    const float mu  = s_sum[0] * (1.f / DIM);
    const float var = s_sq[0] * (1.f / DIM) - mu * mu;
    const float rstd = rsqrtf(var + EPS);

    float* orow = out + (size_t)row * DIM;
    orow[tid]       = (v0 - mu) * rstd * gamma[tid]       + beta[tid];
    orow[tid + 256] = (v1 - mu) * rstd * gamma[tid + 256] + beta[tid + 256];
    orow[tid + 512] = (v2 - mu) * rstd * gamma[tid + 512] + beta[tid + 512];
}

// ---------------- launch ------------------------------------------------------
extern "C" void kernel_launch(void* const* d_in, const int* in_sizes, int n_in,
                              void* d_out, int out_size)
{
    const float* x       = (const float*)d_in[0];
    const float* Wqkv_c  = (const float*)d_in[1];
    const float* bqkv_c  = (const float*)d_in[2];
    const float* Wp_c    = (const float*)d_in[3];
    const float* bp_c    = (const float*)d_in[4];
    const float* Wqkv_ac = (const float*)d_in[5];
    const float* bqkv_ac = (const float*)d_in[6];
    const float* Wp_ac   = (const float*)d_in[7];
    const float* bp_ac   = (const float*)d_in[8];
    const float* gamma   = (const float*)d_in[9];
    const float* beta    = (const float*)d_in[10];
    float* out = (float*)d_out;

    float *qkvc, *qkvac, *attc, *attac, *yb;
    cudaGetSymbolAddress((void**)&qkvc,  g_qkv_c);
    cudaGetSymbolAddress((void**)&qkvac, g_qkv_ac);
    cudaGetSymbolAddress((void**)&attc,  g_att_c);
    cudaGetSymbolAddress((void**)&attac, g_att_ac);
    cudaGetSymbolAddress((void**)&yb,    g_y);

    const int attn_smem = (4 * 64 * APAD + 128) * (int)sizeof(float);
    cudaFuncSetAttribute(attn_kernel, cudaFuncAttributeMaxDynamicSharedMemorySize, attn_smem);

    // QKV projections (tf32 tensor cores)
    dim3 gq(QKVN / GBN, MROWS / GBM);
    gemm_tf32_kernel<<<gq, 256>>>(x, Wqkv_c,  bqkv_c,  nullptr, qkvc,  MROWS, DIM, QKVN, 0);
    gemm_tf32_kernel<<<gq, 256>>>(x, Wqkv_ac, bqkv_ac, nullptr, qkvac, MROWS, DIM, QKVN, 0);

    // attention
    dim3 ga(TSEQ / 64, HEADS, BATCH);
    attn_kernel<<<ga, 128, attn_smem>>>(qkvc,  attc,  1);
    attn_kernel<<<ga, 128, attn_smem>>>(qkvac, attac, 0);

    // output projections fused with residual
    dim3 gp(DIM / GBN, MROWS / GBM);
    gemm_tf32_kernel<<<gp, 256>>>(attc,  Wp_c,  bp_c,  x,       yb, MROWS, DIM, DIM, 0);
    gemm_tf32_kernel<<<gp, 256>>>(attac, Wp_ac, bp_ac, nullptr, yb, MROWS, DIM, DIM, 1);

    // LayerNorm
    ln_kernel<<<MROWS, 256>>>(yb, gamma, beta, out);
}

// round 3
// speedup vs baseline: 3.7412x; 1.5863x over previous
#include <cuda_runtime.h>
#include <cstdint>
#include <cstddef>
#include <math.h>

#define DIM   768
#define TSEQ  1024
#define BATCH 4
#define HEADS 12
#define HDIM  64
#define QKVN  (3 * DIM)      // 2304
#define MROWS (BATCH * TSEQ) // 4096
#define EPS   1e-5f

// ---------------- scratch ------------------------------------------------------
__device__ float g_qkv_c [MROWS * QKVN];
__device__ float g_qkv_ac[MROWS * QKVN];
__device__ float g_att_c [MROWS * DIM];
__device__ float g_att_ac[MROWS * DIM];
__device__ float g_p_c   [MROWS * DIM];
__device__ float g_p_ac  [MROWS * DIM];

// ---------------- mma / cp.async helpers --------------------------------------
__device__ __forceinline__ void mma_tf32(float c[4], const uint32_t a[4], const uint32_t b[2]) {
    asm volatile(
        "mma.sync.aligned.m16n8k8.row.col.f32.tf32.tf32.f32 "
        "{%0,%1,%2,%3}, {%4,%5,%6,%7}, {%8,%9}, {%0,%1,%2,%3};"
        : "+f"(c[0]), "+f"(c[1]), "+f"(c[2]), "+f"(c[3])
        : "r"(a[0]), "r"(a[1]), "r"(a[2]), "r"(a[3]), "r"(b[0]), "r"(b[1]));
}

__device__ __forceinline__ void cp16(uint32_t saddr, const void* gaddr) {
    asm volatile("cp.async.cg.shared.global [%0], [%1], 16;" :: "r"(saddr), "l"(gaddr));
}
__device__ __forceinline__ void cp_commit() { asm volatile("cp.async.commit_group;"); }
template <int N>
__device__ __forceinline__ void cp_wait() { asm volatile("cp.async.wait_group %0;" :: "n"(N)); }

__device__ __forceinline__ uint32_t smem_u32(const void* p) {
    uint32_t a;
    asm("{ .reg .u64 t; cvta.to.shared.u64 t, %1; cvt.u32.u64 %0, t; }" : "=r"(a) : "l"(p));
    return a;
}

// ---------------- tf32 GEMM with cp.async double buffer ------------------------
// C = A[M,K] @ W[K,N] + bias.  blockIdx.z selects branch (A/W/bias/C set).
#define GBM 128
#define GBN 128
#define GBK 32
#define APD (GBK + 4)   // 36
#define BPD (GBN + 4)   // 132
#define GEMM_SMEM ((2 * GBM * APD + 2 * GBK * BPD) * 4)

__global__ void __launch_bounds__(256)
gemm_kernel(const float* __restrict__ A0, const float* __restrict__ A1,
            const float* __restrict__ W0, const float* __restrict__ W1,
            const float* __restrict__ b0, const float* __restrict__ b1,
            float* __restrict__ C0, float* __restrict__ C1,
            int K, int N)
{
    extern __shared__ float sm[];
    float* As = sm;                       // [2][GBM][APD]
    float* Bs = sm + 2 * GBM * APD;       // [2][GBK][BPD]

    const int z = blockIdx.z;
    const float* A    = z ? A1 : A0;
    const float* W    = z ? W1 : W0;
    const float* bias = z ? b1 : b0;
    float*       C    = z ? C1 : C0;

    const int tid  = threadIdx.x;
    const int warp = tid >> 5;
    const int lane = tid & 31;
    const int wr   = warp >> 2;   // 0..1
    const int wc   = warp & 3;    // 0..3
    const int g    = lane >> 2;   // 0..7
    const int t4   = lane & 3;    // 0..3
    const int row0 = blockIdx.y * GBM;
    const int col0 = blockIdx.x * GBN;

    // per-thread load coords
    const int ar = tid >> 3;            // 0..31 (A: 4 rows apart x4 iters -> use idx scheme)
    const int ac = (tid & 7) * 4;
    const int br = tid >> 5;            // 0..7
    const int bc = (tid & 31) * 4;

    auto load_stage = [&](int s, int k0) {
        #pragma unroll
        for (int i = 0; i < 4; i++) {
            int idx = tid + i * 256;
            int r = idx >> 3, c = (idx & 7) * 4;
            cp16(smem_u32(&As[(s * GBM + r) * APD + c]),
                 A + (size_t)(row0 + r) * K + k0 + c);
        }
        #pragma unroll
        for (int i = 0; i < 4; i++) {
            int idx = tid + i * 256;
            int r = idx >> 5, c = (idx & 31) * 4;
            cp16(smem_u32(&Bs[(s * GBK + r) * BPD + c]),
                 W + (size_t)(k0 + r) * N + col0 + c);
        }
        cp_commit();
    };
    (void)ar; (void)ac; (void)br; (void)bc;

    float acc[4][4][4];
    #pragma unroll
    for (int mi = 0; mi < 4; mi++)
        #pragma unroll
        for (int ni = 0; ni < 4; ni++)
            #pragma unroll
            for (int q = 0; q < 4; q++) acc[mi][ni][q] = 0.f;

    const int iters = K / GBK;
    load_stage(0, 0);

    for (int it = 0; it < iters; it++) {
        if (it + 1 < iters) {
            load_stage((it + 1) & 1, (it + 1) * GBK);
            cp_wait<1>();
        } else {
            cp_wait<0>();
        }
        __syncthreads();

        const float* Asb = &As[(it & 1) * GBM * APD];
        const float* Bsb = &Bs[(it & 1) * GBK * BPD];

        #pragma unroll
        for (int ks = 0; ks < 4; ks++) {
            const int kb = ks * 8;
            uint32_t af[4][4];
            #pragma unroll
            for (int mi = 0; mi < 4; mi++) {
                int r = wr * 64 + mi * 16 + g;
                af[mi][0] = __float_as_uint(Asb[r * APD + kb + t4]);
                af[mi][1] = __float_as_uint(Asb[(r + 8) * APD + kb + t4]);
                af[mi][2] = __float_as_uint(Asb[r * APD + kb + t4 + 4]);
                af[mi][3] = __float_as_uint(Asb[(r + 8) * APD + kb + t4 + 4]);
            }
            uint32_t bf[4][2];
            #pragma unroll
            for (int ni = 0; ni < 4; ni++) {
                int c = wc * 32 + ni * 8 + g;
                bf[ni][0] = __float_as_uint(Bsb[(kb + t4) * BPD + c]);
                bf[ni][1] = __float_as_uint(Bsb[(kb + t4 + 4) * BPD + c]);
            }
            #pragma unroll
            for (int mi = 0; mi < 4; mi++)
                #pragma unroll
                for (int ni = 0; ni < 4; ni++)
                    mma_tf32(acc[mi][ni], af[mi], bf[ni]);
        }
        __syncthreads();
    }

    #pragma unroll
    for (int mi = 0; mi < 4; mi++) {
        #pragma unroll
        for (int ni = 0; ni < 4; ni++) {
            int r = row0 + wr * 64 + mi * 16 + g;
            int c = col0 + wc * 32 + ni * 8 + 2 * t4;
            float bv0 = bias[c], bv1 = bias[c + 1];
            *(float2*)(C + (size_t)r * N + c) =
                make_float2(acc[mi][ni][0] + bv0, acc[mi][ni][1] + bv1);
            *(float2*)(C + (size_t)(r + 8) * N + c) =
                make_float2(acc[mi][ni][2] + bv0, acc[mi][ni][3] + bv1);
        }
    }
}

// ---------------- tf32 tensor-core flash attention -----------------------------
// grid (T/64, HEADS, 2*BATCH): z>>2 selects branch, z&3 = batch.
// 128 threads = 4 warps; warp w owns rows w*16..w*16+15 of the 64-row q tile.
#define AP 68
#define ATTN_SMEM (3 * 64 * AP * 4)

__global__ void __launch_bounds__(128)
attn_kernel(const float* __restrict__ qkv_c, const float* __restrict__ qkv_ac,
            float* __restrict__ out_c, float* __restrict__ out_ac)
{
    extern __shared__ float sm[];
    float* Ks = sm;               // [64][AP] K natural [j][d]
    float* Vt = sm + 64 * AP;     // [64][AP] V transposed [d][j]
    float* Ps = sm + 128 * AP;    // [64][AP] P (per-warp rows) / Q staging

    const int tid  = threadIdx.x;
    const int w    = tid >> 5;
    const int lane = tid & 31;
    const int g    = lane >> 2;
    const int t4   = lane & 3;
    const int rw   = tid >> 1;
    const int half = tid & 1;

    const int qt = blockIdx.x, h = blockIdx.y, z = blockIdx.z;
    const int b = z & 3;
    const int branch = z >> 2;          // 0 causal, 1 anti-causal
    const bool causal = (branch == 0);
    const float* qkv = branch ? qkv_ac : qkv_c;
    float*       out = branch ? out_ac : out_c;

    // ---- stage Q (scaled) into Ps, pull fragments into registers ----
    {
        const float* qp = qkv + (size_t)(b * TSEQ + qt * 64 + rw) * QKVN + h * HDIM + half * 32;
        float4* dst = (float4*)&Ps[rw * AP + half * 32];
        #pragma unroll
        for (int i = 0; i < 8; i++) {
            float4 f = ((const float4*)qp)[i];
            f.x *= 0.125f; f.y *= 0.125f; f.z *= 0.125f; f.w *= 0.125f;
            dst[i] = f;
        }
    }
    __syncthreads();
    uint32_t qf[8][4];
    {
        const int r0 = (w * 16 + g) * AP;
        const int r8 = r0 + 8 * AP;
        #pragma unroll
        for (int kb = 0; kb < 8; kb++) {
            qf[kb][0] = __float_as_uint(Ps[r0 + kb * 8 + t4]);
            qf[kb][1] = __float_as_uint(Ps[r8 + kb * 8 + t4]);
            qf[kb][2] = __float_as_uint(Ps[r0 + kb * 8 + t4 + 4]);
            qf[kb][3] = __float_as_uint(Ps[r8 + kb * 8 + t4 + 4]);
        }
    }
    __syncthreads();

    float m0 = -INFINITY, m1 = -INFINITY, l0 = 0.f, l1 = 0.f;
    float oacc[8][4];
    #pragma unroll
    for (int nt = 0; nt < 8; nt++)
        #pragma unroll
        for (int q = 0; q < 4; q++) oacc[nt][q] = 0.f;

    const int kt0 = causal ? 0  : qt;
    const int kt1 = causal ? qt : (TSEQ / 64 - 1);
    const int ig0 = qt * 64 + w * 16 + g;
    const int ig1 = ig0 + 8;

    for (int kt = kt0; kt <= kt1; kt++) {
        // ---- load K (natural) and V (transposed) tiles ----
        {
            const float* kp = qkv + (size_t)(b * TSEQ + kt * 64 + rw) * QKVN
                              + DIM + h * HDIM + half * 32;
            const float* vp = kp + DIM;
            float4* kd = (float4*)&Ks[rw * AP + half * 32];
            #pragma unroll
            for (int i = 0; i < 8; i++) {
                kd[i] = ((const float4*)kp)[i];
                float4 f = ((const float4*)vp)[i];
                int d = half * 32 + i * 4;
                Vt[(d + 0) * AP + rw] = f.x;
                Vt[(d + 1) * AP + rw] = f.y;
                Vt[(d + 2) * AP + rw] = f.z;
                Vt[(d + 3) * AP + rw] = f.w;
            }
        }
        __syncthreads();

        // ---- S = Q K^T  (warp rows x all 64 keys) ----
        float sacc[8][4];
        #pragma unroll
        for (int nt = 0; nt < 8; nt++)
            #pragma unroll
            for (int q = 0; q < 4; q++) sacc[nt][q] = 0.f;

        #pragma unroll
        for (int kb = 0; kb < 8; kb++) {
            uint32_t bf[8][2];
            #pragma unroll
            for (int nt = 0; nt < 8; nt++) {
                int jr = (nt * 8 + g) * AP + kb * 8;
                bf[nt][0] = __float_as_uint(Ks[jr + t4]);
                bf[nt][1] = __float_as_uint(Ks[jr + t4 + 4]);
            }
            #pragma unroll
            for (int nt = 0; nt < 8; nt++)
                mma_tf32(sacc[nt], qf[kb], bf[nt]);
        }

        // ---- mask diagonal tile ----
        if (kt == qt) {
            #pragma unroll
            for (int nt = 0; nt < 8; nt++) {
                int jg = kt * 64 + nt * 8 + 2 * t4;
                if (causal) {
                    if (jg     > ig0) sacc[nt][0] = -INFINITY;
                    if (jg + 1 > ig0) sacc[nt][1] = -INFINITY;
                    if (jg     > ig1) sacc[nt][2] = -INFINITY;
                    if (jg + 1 > ig1) sacc[nt][3] = -INFINITY;
                } else {
                    if (jg     < ig0) sacc[nt][0] = -INFINITY;
                    if (jg + 1 < ig0) sacc[nt][1] = -INFINITY;
                    if (jg     < ig1) sacc[nt][2] = -INFINITY;
                    if (jg + 1 < ig1) sacc[nt][3] = -INFINITY;
                }
            }
        }

        // ---- online softmax (register, rows g / g+8) ----
        float tm0 = -INFINITY, tm1 = -INFINITY;
        #pragma unroll
        for (int nt = 0; nt < 8; nt++) {
            tm0 = fmaxf(tm0, fmaxf(sacc[nt][0], sacc[nt][1]));
            tm1 = fmaxf(tm1, fmaxf(sacc[nt][2], sacc[nt][3]));
        }
        tm0 = fmaxf(tm0, __shfl_xor_sync(0xffffffffu, tm0, 1));
        tm0 = fmaxf(tm0, __shfl_xor_sync(0xffffffffu, tm0, 2));
        tm1 = fmaxf(tm1, __shfl_xor_sync(0xffffffffu, tm1, 1));
        tm1 = fmaxf(tm1, __shfl_xor_sync(0xffffffffu, tm1, 2));

        float mn0 = fmaxf(m0, tm0), mn1 = fmaxf(m1, tm1);
        float corr0 = __expf(m0 - mn0), corr1 = __expf(m1 - mn1);
        m0 = mn0; m1 = mn1;

        float ps0 = 0.f, ps1 = 0.f;
        #pragma unroll
        for (int nt = 0; nt < 8; nt++) {
            sacc[nt][0] = __expf(sacc[nt][0] - mn0); ps0 += sacc[nt][0];
            sacc[nt][1] = __expf(sacc[nt][1] - mn0); ps0 += sacc[nt][1];
            sacc[nt][2] = __expf(sacc[nt][2] - mn1); ps1 += sacc[nt][2];
            sacc[nt][3] = __expf(sacc[nt][3] - mn1); ps1 += sacc[nt][3];
        }
        ps0 += __shfl_xor_sync(0xffffffffu, ps0, 1);
        ps0 += __shfl_xor_sync(0xffffffffu, ps0, 2);
        ps1 += __shfl_xor_sync(0xffffffffu, ps1, 1);
        ps1 += __shfl_xor_sync(0xffffffffu, ps1, 2);
        l0 = l0 * corr0 + ps0;
        l1 = l1 * corr1 + ps1;

        // ---- write P to per-warp smem rows ----
        {
            const int r0 = (w * 16 + g) * AP + 2 * t4;
            const int r8 = r0 + 8 * AP;
            #pragma unroll
            for (int nt = 0; nt < 8; nt++) {
                *(float2*)&Ps[r0 + nt * 8] = make_float2(sacc[nt][0], sacc[nt][1]);
                *(float2*)&Ps[r8 + nt * 8] = make_float2(sacc[nt][2], sacc[nt][3]);
            }
        }
        __syncwarp();

        // ---- rescale O ----
        #pragma unroll
        for (int nt = 0; nt < 8; nt++) {
            oacc[nt][0] *= corr0; oacc[nt][1] *= corr0;
            oacc[nt][2] *= corr1; oacc[nt][3] *= corr1;
        }

        // ---- O += P V ----
        #pragma unroll
        for (int kb = 0; kb < 8; kb++) {
            uint32_t af[4];
            {
                const int pr = (w * 16 + g) * AP + kb * 8;
                const int p8 = pr + 8 * AP;
                af[0] = __float_as_uint(Ps[pr + t4]);
                af[1] = __float_as_uint(Ps[p8 + t4]);
                af[2] = __float_as_uint(Ps[pr + t4 + 4]);
                af[3] = __float_as_uint(Ps[p8 + t4 + 4]);
            }
            uint32_t bf[8][2];
            #pragma unroll
            for (int nt = 0; nt < 8; nt++) {
                int vr = (nt * 8 + g) * AP + kb * 8;
                bf[nt][0] = __float_as_uint(Vt[vr + t4]);
                bf[nt][1] = __float_as_uint(Vt[vr + t4 + 4]);
            }
            #pragma unroll
            for (int nt = 0; nt < 8; nt++)
                mma_tf32(oacc[nt], af, bf[nt]);
        }
        __syncthreads();
    }

    // ---- epilogue ----
    const float inv0 = 1.f / l0;
    const float inv1 = 1.f / l1;
    const size_t row0g = (size_t)(b * TSEQ) + ig0;
    const size_t row1g = row0g + 8;
    #pragma unroll
    for (int nt = 0; nt < 8; nt++) {
        int c = h * HDIM + nt * 8 + 2 * t4;
        *(float2*)(out + row0g * DIM + c) =
            make_float2(oacc[nt][0] * inv0, oacc[nt][1] * inv0);
        *(float2*)(out + row1g * DIM + c) =
            make_float2(oacc[nt][2] * inv1, oacc[nt][3] * inv1);
    }
}

// ---------------- LayerNorm over x + pc + pac ----------------------------------
__global__ void ln_kernel(const float* __restrict__ x,
                          const float* __restrict__ pc,
                          const float* __restrict__ pac,
                          const float* __restrict__ gamma,
                          const float* __restrict__ beta,
                          float* __restrict__ out)
{
    __shared__ float s_sum[256];
    __shared__ float s_sq[256];
    const int row = blockIdx.x;
    const int tid = threadIdx.x;
    const size_t base = (size_t)row * DIM;

    float v0 = x[base + tid]       + pc[base + tid]       + pac[base + tid];
    float v1 = x[base + tid + 256] + pc[base + tid + 256] + pac[base + tid + 256];
    float v2 = x[base + tid + 512] + pc[base + tid + 512] + pac[base + tid + 512];
    float su = v0 + v1 + v2;
    float sq = v0 * v0 + v1 * v1 + v2 * v2;
    s_sum[tid] = su; s_sq[tid] = sq;
    __syncthreads();
    for (int off = 128; off > 0; off >>= 1) {
        if (tid < off) { s_sum[tid] += s_sum[tid + off]; s_sq[tid] += s_sq[tid + off]; }
        __syncthreads();
    }
    const float mu  = s_sum[0] * (1.f / DIM);
    const float var = s_sq[0] * (1.f / DIM) - mu * mu;
    const float rstd = rsqrtf(var + EPS);

    out[base + tid]       = (v0 - mu) * rstd * gamma[tid]       + beta[tid];
    out[base + tid + 256] = (v1 - mu) * rstd * gamma[tid + 256] + beta[tid + 256];
    out[base + tid + 512] = (v2 - mu) * rstd * gamma[tid + 512] + beta[tid + 512];
}

// ---------------- launch --------------------------------------------------------
extern "C" void kernel_launch(void* const* d_in, const int* in_sizes, int n_in,
                              void* d_out, int out_size)
{
    const float* x       = (const float*)d_in[0];
    const float* Wqkv_c  = (const float*)d_in[1];
    const float* bqkv_c  = (const float*)d_in[2];
    const float* Wp_c    = (const float*)d_in[3];
    const float* bp_c    = (const float*)d_in[4];
    const float* Wqkv_ac = (const float*)d_in[5];
    const float* bqkv_ac = (const float*)d_in[6];
    const float* Wp_ac   = (const float*)d_in[7];
    const float* bp_ac   = (const float*)d_in[8];
    const float* gamma   = (const float*)d_in[9];
    const float* beta    = (const float*)d_in[10];
    float* out = (float*)d_out;

    float *qkvc, *qkvac, *attc, *attac, *pc, *pac;
    cudaGetSymbolAddress((void**)&qkvc,  g_qkv_c);
    cudaGetSymbolAddress((void**)&qkvac, g_qkv_ac);
    cudaGetSymbolAddress((void**)&attc,  g_att_c);
    cudaGetSymbolAddress((void**)&attac, g_att_ac);
    cudaGetSymbolAddress((void**)&pc,    g_p_c);
    cudaGetSymbolAddress((void**)&pac,   g_p_ac);

    static int configured = 0;
    if (!configured) {
        cudaFuncSetAttribute(gemm_kernel, cudaFuncAttributeMaxDynamicSharedMemorySize, GEMM_SMEM);
        cudaFuncSetAttribute(attn_kernel, cudaFuncAttributeMaxDynamicSharedMemorySize, ATTN_SMEM);
        configured = 1;
    }

    // QKV projections, both branches in one launch
    dim3 gq(QKVN / GBN, MROWS / GBM, 2);
    gemm_kernel<<<gq, 256, GEMM_SMEM>>>(x, x, Wqkv_c, Wqkv_ac, bqkv_c, bqkv_ac,
                                        qkvc, qkvac, DIM, QKVN);

    // attention, both branches in one launch
    dim3 ga(TSEQ / 64, HEADS, 2 * BATCH);
    attn_kernel<<<ga, 128, ATTN_SMEM>>>(qkvc, qkvac, attc, attac);

    // output projections, both branches in one launch
    dim3 gp(DIM / GBN, MROWS / GBM, 2);
    gemm_kernel<<<gp, 256, GEMM_SMEM>>>(attc, attac, Wp_c, Wp_ac, bp_c, bp_ac,
                                        pc, pac, DIM, DIM);

    // residual + LayerNorm
    ln_kernel<<<MROWS, 256>>>(x, pc, pac, gamma, beta, out);
}

// round 4
// speedup vs baseline: 4.5199x; 1.2081x over previous
#include <cuda_runtime.h>
#include <cstdint>
#include <cstddef>
#include <math.h>

#define DIM   768
#define TSEQ  1024
#define BATCH 4
#define HEADS 12
#define HDIM  64
#define QKVN  (3 * DIM)      // 2304
#define MROWS (BATCH * TSEQ) // 4096
#define EPS   1e-5f

// ---------------- scratch ------------------------------------------------------
__device__ float g_qkv_c [MROWS * QKVN];
__device__ float g_qkv_ac[MROWS * QKVN];
__device__ float g_att_c [MROWS * DIM];
__device__ float g_att_ac[MROWS * DIM];
__device__ float g_p_c   [MROWS * DIM];
__device__ float g_p_ac  [MROWS * DIM];

// ---------------- mma / cp.async helpers --------------------------------------
__device__ __forceinline__ void mma_tf32(float c[4], const uint32_t a[4], const uint32_t b[2]) {
    asm volatile(
        "mma.sync.aligned.m16n8k8.row.col.f32.tf32.tf32.f32 "
        "{%0,%1,%2,%3}, {%4,%5,%6,%7}, {%8,%9}, {%0,%1,%2,%3};"
        : "+f"(c[0]), "+f"(c[1]), "+f"(c[2]), "+f"(c[3])
        : "r"(a[0]), "r"(a[1]), "r"(a[2]), "r"(a[3]), "r"(b[0]), "r"(b[1]));
}

__device__ __forceinline__ void cp16(uint32_t saddr, const void* gaddr) {
    asm volatile("cp.async.cg.shared.global [%0], [%1], 16;" :: "r"(saddr), "l"(gaddr));
}
__device__ __forceinline__ void cp_commit() { asm volatile("cp.async.commit_group;"); }
template <int N>
__device__ __forceinline__ void cp_wait() { asm volatile("cp.async.wait_group %0;" :: "n"(N)); }

__device__ __forceinline__ uint32_t smem_u32(const void* p) {
    uint32_t a;
    asm("{ .reg .u64 t; cvta.to.shared.u64 t, %1; cvt.u32.u64 %0, t; }" : "=r"(a) : "l"(p));
    return a;
}

// ---------------- tf32 GEMM with cp.async double buffer ------------------------
#define GBM 128
#define GBN 128
#define GBK 32
#define APD (GBK + 4)   // 36: A-frag banks 4g+t4 -> conflict-free
#define BPD (GBN + 8)   // 136: B-frag banks 8t4+g -> conflict-free
#define GEMM_SMEM ((2 * GBM * APD + 2 * GBK * BPD) * 4)

__global__ void __launch_bounds__(256)
gemm_kernel(const float* __restrict__ A0, const float* __restrict__ A1,
            const float* __restrict__ W0, const float* __restrict__ W1,
            const float* __restrict__ b0, const float* __restrict__ b1,
            float* __restrict__ C0, float* __restrict__ C1,
            int K, int N)
{
    extern __shared__ float sm[];
    float* As = sm;                       // [2][GBM][APD]
    float* Bs = sm + 2 * GBM * APD;       // [2][GBK][BPD]

    const int z = blockIdx.z;
    const float* A    = z ? A1 : A0;
    const float* W    = z ? W1 : W0;
    const float* bias = z ? b1 : b0;
    float*       C    = z ? C1 : C0;

    const int tid  = threadIdx.x;
    const int warp = tid >> 5;
    const int lane = tid & 31;
    const int wr   = warp >> 2;
    const int wc   = warp & 3;
    const int g    = lane >> 2;
    const int t4   = lane & 3;
    const int row0 = blockIdx.y * GBM;
    const int col0 = blockIdx.x * GBN;

    auto load_stage = [&](int s, int k0) {
        #pragma unroll
        for (int i = 0; i < 4; i++) {
            int idx = tid + i * 256;
            int r = idx >> 3, c = (idx & 7) * 4;
            cp16(smem_u32(&As[(s * GBM + r) * APD + c]),
                 A + (size_t)(row0 + r) * K + k0 + c);
        }
        #pragma unroll
        for (int i = 0; i < 4; i++) {
            int idx = tid + i * 256;
            int r = idx >> 5, c = (idx & 31) * 4;
            cp16(smem_u32(&Bs[(s * GBK + r) * BPD + c]),
                 W + (size_t)(k0 + r) * N + col0 + c);
        }
        cp_commit();
    };

    float acc[4][4][4];
    #pragma unroll
    for (int mi = 0; mi < 4; mi++)
        #pragma unroll
        for (int ni = 0; ni < 4; ni++)
            #pragma unroll
            for (int q = 0; q < 4; q++) acc[mi][ni][q] = 0.f;

    const int iters = K / GBK;
    load_stage(0, 0);

    for (int it = 0; it < iters; it++) {
        if (it + 1 < iters) {
            load_stage((it + 1) & 1, (it + 1) * GBK);
            cp_wait<1>();
        } else {
            cp_wait<0>();
        }
        __syncthreads();

        const float* Asb = &As[(it & 1) * GBM * APD];
        const float* Bsb = &Bs[(it & 1) * GBK * BPD];

        #pragma unroll
        for (int ks = 0; ks < 4; ks++) {
            const int kb = ks * 8;
            uint32_t af[4][4];
            #pragma unroll
            for (int mi = 0; mi < 4; mi++) {
                int r = wr * 64 + mi * 16 + g;
                af[mi][0] = __float_as_uint(Asb[r * APD + kb + t4]);
                af[mi][1] = __float_as_uint(Asb[(r + 8) * APD + kb + t4]);
                af[mi][2] = __float_as_uint(Asb[r * APD + kb + t4 + 4]);
                af[mi][3] = __float_as_uint(Asb[(r + 8) * APD + kb + t4 + 4]);
            }
            uint32_t bf[4][2];
            #pragma unroll
            for (int ni = 0; ni < 4; ni++) {
                int c = wc * 32 + ni * 8 + g;
                bf[ni][0] = __float_as_uint(Bsb[(kb + t4) * BPD + c]);
                bf[ni][1] = __float_as_uint(Bsb[(kb + t4 + 4) * BPD + c]);
            }
            #pragma unroll
            for (int mi = 0; mi < 4; mi++)
                #pragma unroll
                for (int ni = 0; ni < 4; ni++)
                    mma_tf32(acc[mi][ni], af[mi], bf[ni]);
        }
        __syncthreads();
    }

    #pragma unroll
    for (int mi = 0; mi < 4; mi++) {
        #pragma unroll
        for (int ni = 0; ni < 4; ni++) {
            int r = row0 + wr * 64 + mi * 16 + g;
            int c = col0 + wc * 32 + ni * 8 + 2 * t4;
            float bv0 = bias[c], bv1 = bias[c + 1];
            *(float2*)(C + (size_t)r * N + c) =
                make_float2(acc[mi][ni][0] + bv0, acc[mi][ni][1] + bv1);
            *(float2*)(C + (size_t)(r + 8) * N + c) =
                make_float2(acc[mi][ni][2] + bv0, acc[mi][ni][3] + bv1);
        }
    }
}

// ---------------- tf32 tensor-core flash attention -----------------------------
// grid (T/128, HEADS, 2*BATCH). 256 threads = 8 warps; warp w owns q rows
// w*16..w*16+15 of a 128-row q tile. Key tile = 64. V stored naturally
// (B-fragment of P@V reads V[j][d] directly; pad 72 makes it conflict-free).
#define APK 68
#define APV 72
#define ATTN_SMEM ((64 * APK + 64 * APV + 128 * APK) * 4)

__global__ void __launch_bounds__(256, 2)
attn_kernel(const float* __restrict__ qkv_c, const float* __restrict__ qkv_ac,
            float* __restrict__ out_c, float* __restrict__ out_ac)
{
    extern __shared__ float sm[];
    float* Ks = sm;                    // [64][APK]   K natural [j][d]
    float* Vs = Ks + 64 * APK;         // [64][APV]   V natural [j][d]
    float* Ps = Vs + 64 * APV;         // [128][APK]  Q staging / per-warp P

    const int tid  = threadIdx.x;
    const int w    = tid >> 5;
    const int lane = tid & 31;
    const int g    = lane >> 2;
    const int t4   = lane & 3;

    const int qt = blockIdx.x, h = blockIdx.y, z = blockIdx.z;
    const int b = z & 3;
    const int branch = z >> 2;
    const bool causal = (branch == 0);
    const float* qkv = branch ? qkv_ac : qkv_c;
    float*       out = branch ? out_ac : out_c;

    // ---- stage Q (scaled); rows are warp-private (row r written by warp r>>4) ----
    {
        const int rw = tid >> 1, half = tid & 1;
        const float* qp = qkv + (size_t)(b * TSEQ + qt * 128 + rw) * QKVN + h * HDIM + half * 32;
        float4* dst = (float4*)&Ps[rw * APK + half * 32];
        #pragma unroll
        for (int i = 0; i < 8; i++) {
            float4 f = ((const float4*)qp)[i];
            f.x *= 0.125f; f.y *= 0.125f; f.z *= 0.125f; f.w *= 0.125f;
            dst[i] = f;
        }
    }
    __syncwarp();
    uint32_t qf[8][4];
    {
        const int r0 = (w * 16 + g) * APK;
        const int r8 = r0 + 8 * APK;
        #pragma unroll
        for (int kb = 0; kb < 8; kb++) {
            qf[kb][0] = __float_as_uint(Ps[r0 + kb * 8 + t4]);
            qf[kb][1] = __float_as_uint(Ps[r8 + kb * 8 + t4]);
            qf[kb][2] = __float_as_uint(Ps[r0 + kb * 8 + t4 + 4]);
            qf[kb][3] = __float_as_uint(Ps[r8 + kb * 8 + t4 + 4]);
        }
    }

    float m0 = -INFINITY, m1 = -INFINITY, l0 = 0.f, l1 = 0.f;
    float oacc[8][4];
    #pragma unroll
    for (int nt = 0; nt < 8; nt++)
        #pragma unroll
        for (int q = 0; q < 4; q++) oacc[nt][q] = 0.f;

    const int diag_kt = 2 * qt + (w >> 2);       // each warp's rows sit in one 64-key diag tile
    const int ig0 = qt * 128 + w * 16 + g;
    const int ig1 = ig0 + 8;
    const int kt0 = causal ? 0 : 2 * qt;
    const int kt1 = causal ? 2 * qt + 1 : (TSEQ / 64 - 1);

    for (int kt = kt0; kt <= kt1; kt++) {
        // ---- cooperative K/V load (natural layouts, float4) ----
        {
            const int row = tid >> 2, q4 = tid & 3;
            const float* kp = qkv + (size_t)(b * TSEQ + kt * 64 + row) * QKVN
                              + DIM + h * HDIM + q4 * 16;
            const float* vp = kp + DIM;
            float4* kd = (float4*)&Ks[row * APK + q4 * 16];
            float4* vd = (float4*)&Vs[row * APV + q4 * 16];
            #pragma unroll
            for (int i = 0; i < 4; i++) {
                kd[i] = ((const float4*)kp)[i];
                vd[i] = ((const float4*)vp)[i];
            }
        }
        __syncthreads();

        const bool active = causal ? (kt <= diag_kt) : (kt >= diag_kt);
        if (active) {
            // ---- S = Q K^T ----
            float sacc[8][4];
            #pragma unroll
            for (int nt = 0; nt < 8; nt++)
                #pragma unroll
                for (int q = 0; q < 4; q++) sacc[nt][q] = 0.f;

            #pragma unroll
            for (int kb = 0; kb < 8; kb++) {
                uint32_t bf[8][2];
                #pragma unroll
                for (int nt = 0; nt < 8; nt++) {
                    int jr = (nt * 8 + g) * APK + kb * 8;
                    bf[nt][0] = __float_as_uint(Ks[jr + t4]);
                    bf[nt][1] = __float_as_uint(Ks[jr + t4 + 4]);
                }
                #pragma unroll
                for (int nt = 0; nt < 8; nt++)
                    mma_tf32(sacc[nt], qf[kb], bf[nt]);
            }

            // ---- mask diagonal tile ----
            if (kt == diag_kt) {
                #pragma unroll
                for (int nt = 0; nt < 8; nt++) {
                    int jg = kt * 64 + nt * 8 + 2 * t4;
                    if (causal) {
                        if (jg     > ig0) sacc[nt][0] = -INFINITY;
                        if (jg + 1 > ig0) sacc[nt][1] = -INFINITY;
                        if (jg     > ig1) sacc[nt][2] = -INFINITY;
                        if (jg + 1 > ig1) sacc[nt][3] = -INFINITY;
                    } else {
                        if (jg     < ig0) sacc[nt][0] = -INFINITY;
                        if (jg + 1 < ig0) sacc[nt][1] = -INFINITY;
                        if (jg     < ig1) sacc[nt][2] = -INFINITY;
                        if (jg + 1 < ig1) sacc[nt][3] = -INFINITY;
                    }
                }
            }

            // ---- online softmax ----
            float tm0 = -INFINITY, tm1 = -INFINITY;
            #pragma unroll
            for (int nt = 0; nt < 8; nt++) {
                tm0 = fmaxf(tm0, fmaxf(sacc[nt][0], sacc[nt][1]));
                tm1 = fmaxf(tm1, fmaxf(sacc[nt][2], sacc[nt][3]));
            }
            tm0 = fmaxf(tm0, __shfl_xor_sync(0xffffffffu, tm0, 1));
            tm0 = fmaxf(tm0, __shfl_xor_sync(0xffffffffu, tm0, 2));
            tm1 = fmaxf(tm1, __shfl_xor_sync(0xffffffffu, tm1, 1));
            tm1 = fmaxf(tm1, __shfl_xor_sync(0xffffffffu, tm1, 2));

            float mn0 = fmaxf(m0, tm0), mn1 = fmaxf(m1, tm1);
            float corr0 = __expf(m0 - mn0), corr1 = __expf(m1 - mn1);
            m0 = mn0; m1 = mn1;

            float ps0 = 0.f, ps1 = 0.f;
            #pragma unroll
            for (int nt = 0; nt < 8; nt++) {
                sacc[nt][0] = __expf(sacc[nt][0] - mn0); ps0 += sacc[nt][0];
                sacc[nt][1] = __expf(sacc[nt][1] - mn0); ps0 += sacc[nt][1];
                sacc[nt][2] = __expf(sacc[nt][2] - mn1); ps1 += sacc[nt][2];
                sacc[nt][3] = __expf(sacc[nt][3] - mn1); ps1 += sacc[nt][3];
            }
            ps0 += __shfl_xor_sync(0xffffffffu, ps0, 1);
            ps0 += __shfl_xor_sync(0xffffffffu, ps0, 2);
            ps1 += __shfl_xor_sync(0xffffffffu, ps1, 1);
            ps1 += __shfl_xor_sync(0xffffffffu, ps1, 2);
            l0 = l0 * corr0 + ps0;
            l1 = l1 * corr1 + ps1;

            // ---- write P into this warp's private Ps rows ----
            {
                const int r0 = (w * 16 + g) * APK + 2 * t4;
                const int r8 = r0 + 8 * APK;
                #pragma unroll
                for (int nt = 0; nt < 8; nt++) {
                    *(float2*)&Ps[r0 + nt * 8] = make_float2(sacc[nt][0], sacc[nt][1]);
                    *(float2*)&Ps[r8 + nt * 8] = make_float2(sacc[nt][2], sacc[nt][3]);
                }
            }
            __syncwarp();

            // ---- rescale O, then O += P V ----
            #pragma unroll
            for (int nt = 0; nt < 8; nt++) {
                oacc[nt][0] *= corr0; oacc[nt][1] *= corr0;
                oacc[nt][2] *= corr1; oacc[nt][3] *= corr1;
            }
            #pragma unroll
            for (int kb = 0; kb < 8; kb++) {
                uint32_t af[4];
                {
                    const int pr = (w * 16 + g) * APK + kb * 8;
                    const int p8 = pr + 8 * APK;
                    af[0] = __float_as_uint(Ps[pr + t4]);
                    af[1] = __float_as_uint(Ps[p8 + t4]);
                    af[2] = __float_as_uint(Ps[pr + t4 + 4]);
                    af[3] = __float_as_uint(Ps[p8 + t4 + 4]);
                }
                uint32_t bf[8][2];
                #pragma unroll
                for (int nt = 0; nt < 8; nt++) {
                    bf[nt][0] = __float_as_uint(Vs[(kb * 8 + t4) * APV + nt * 8 + g]);
                    bf[nt][1] = __float_as_uint(Vs[(kb * 8 + t4 + 4) * APV + nt * 8 + g]);
                }
                #pragma unroll
                for (int nt = 0; nt < 8; nt++)
                    mma_tf32(oacc[nt], af, bf[nt]);
            }
        }
        __syncthreads();
    }

    // ---- epilogue ----
    const float inv0 = 1.f / l0;
    const float inv1 = 1.f / l1;
    const size_t row0g = (size_t)(b * TSEQ) + ig0;
    const size_t row1g = row0g + 8;
    #pragma unroll
    for (int nt = 0; nt < 8; nt++) {
        int c = h * HDIM + nt * 8 + 2 * t4;
        *(float2*)(out + row0g * DIM + c) =
            make_float2(oacc[nt][0] * inv0, oacc[nt][1] * inv0);
        *(float2*)(out + row1g * DIM + c) =
            make_float2(oacc[nt][2] * inv1, oacc[nt][3] * inv1);
    }
}

// ---------------- LayerNorm over x + pc + pac (float4, warp-reduce) ------------
__global__ void __launch_bounds__(192)
ln_kernel(const float* __restrict__ x,
          const float* __restrict__ pc,
          const float* __restrict__ pac,
          const float* __restrict__ gamma,
          const float* __restrict__ beta,
          float* __restrict__ out)
{
    __shared__ float s_red[12];      // 6 warps x {sum, sq}
    __shared__ float s_stat[2];
    const int row = blockIdx.x;
    const int tid = threadIdx.x;
    const size_t base = (size_t)row * DIM + tid * 4;

    float4 a = *(const float4*)(x + base);
    float4 p = *(const float4*)(pc + base);
    float4 q = *(const float4*)(pac + base);
    float4 v = make_float4(a.x + p.x + q.x, a.y + p.y + q.y,
                           a.z + p.z + q.z, a.w + p.w + q.w);
    float su = v.x + v.y + v.z + v.w;
    float sq = v.x * v.x + v.y * v.y + v.z * v.z + v.w * v.w;
    #pragma unroll
    for (int off = 16; off > 0; off >>= 1) {
        su += __shfl_xor_sync(0xffffffffu, su, off);
        sq += __shfl_xor_sync(0xffffffffu, sq, off);
    }
    const int wi = tid >> 5;
    if ((tid & 31) == 0) { s_red[wi] = su; s_red[wi + 6] = sq; }
    __syncthreads();
    if (tid == 0) {
        float ts = 0.f, tq = 0.f;
        #pragma unroll
        for (int i = 0; i < 6; i++) { ts += s_red[i]; tq += s_red[i + 6]; }
        float mu  = ts * (1.f / DIM);
        float var = tq * (1.f / DIM) - mu * mu;
        s_stat[0] = mu;
        s_stat[1] = rsqrtf(var + EPS);
    }
    __syncthreads();
    const float mu = s_stat[0], rstd = s_stat[1];
    float4 gm = *(const float4*)(gamma + tid * 4);
    float4 bt = *(const float4*)(beta  + tid * 4);
    float4 o;
    o.x = (v.x - mu) * rstd * gm.x + bt.x;
    o.y = (v.y - mu) * rstd * gm.y + bt.y;
    o.z = (v.z - mu) * rstd * gm.z + bt.z;
    o.w = (v.w - mu) * rstd * gm.w + bt.w;
    *(float4*)(out + base) = o;
}

// ---------------- launch --------------------------------------------------------
extern "C" void kernel_launch(void* const* d_in, const int* in_sizes, int n_in,
                              void* d_out, int out_size)
{
    const float* x       = (const float*)d_in[0];
    const float* Wqkv_c  = (const float*)d_in[1];
    const float* bqkv_c  = (const float*)d_in[2];
    const float* Wp_c    = (const float*)d_in[3];
    const float* bp_c    = (const float*)d_in[4];
    const float* Wqkv_ac = (const float*)d_in[5];
    const float* bqkv_ac = (const float*)d_in[6];
    const float* Wp_ac   = (const float*)d_in[7];
    const float* bp_ac   = (const float*)d_in[8];
    const float* gamma   = (const float*)d_in[9];
    const float* beta    = (const float*)d_in[10];
    float* out = (float*)d_out;

    float *qkvc, *qkvac, *attc, *attac, *pc, *pac;
    cudaGetSymbolAddress((void**)&qkvc,  g_qkv_c);
    cudaGetSymbolAddress((void**)&qkvac, g_qkv_ac);
    cudaGetSymbolAddress((void**)&attc,  g_att_c);
    cudaGetSymbolAddress((void**)&attac, g_att_ac);
    cudaGetSymbolAddress((void**)&pc,    g_p_c);
    cudaGetSymbolAddress((void**)&pac,   g_p_ac);

    static int configured = 0;
    if (!configured) {
        cudaFuncSetAttribute(gemm_kernel, cudaFuncAttributeMaxDynamicSharedMemorySize, GEMM_SMEM);
        cudaFuncSetAttribute(attn_kernel, cudaFuncAttributeMaxDynamicSharedMemorySize, ATTN_SMEM);
        configured = 1;
    }

    // QKV projections, both branches
    dim3 gq(QKVN / GBN, MROWS / GBM, 2);
    gemm_kernel<<<gq, 256, GEMM_SMEM>>>(x, x, Wqkv_c, Wqkv_ac, bqkv_c, bqkv_ac,
                                        qkvc, qkvac, DIM, QKVN);

    // attention, both branches, 128-row q tiles
    dim3 ga(TSEQ / 128, HEADS, 2 * BATCH);
    attn_kernel<<<ga, 256, ATTN_SMEM>>>(qkvc, qkvac, attc, attac);

    // output projections, both branches
    dim3 gp(DIM / GBN, MROWS / GBM, 2);
    gemm_kernel<<<gp, 256, GEMM_SMEM>>>(attc, attac, Wp_c, Wp_ac, bp_c, bp_ac,
                                        pc, pac, DIM, DIM);

    // residual + LayerNorm
    ln_kernel<<<MROWS, 192>>>(x, pc, pac, gamma, beta, out);
}